// round 10
// baseline (speedup 1.0000x reference)
#include <cuda_runtime.h>
#include <cuda_fp16.h>
#include <math.h>

#define Nn 50000
#define Ee 1600000
#define DIN 128
#define DH 64
#define BN_EPS 1e-5f
#define GEMM_BLKS 592

// ---------------- scratch (device globals; no allocation allowed) -------------
__device__ float  g_w[Ee];            // mixed weight (pre-norm)
__device__ int2   g_idx[Ee];          // (src, dst) as int32
__device__ int2   g_csr[Ee];          // dst-sorted: (src, bitcast(norm))
__device__ float2 g_degcnt[Nn];       // (weighted degree incl self, count) via red.v2
__device__ float  g_dinv[Nn];         // rsqrt(deg)
__device__ int    g_part[50176];      // block-local exclusive scan
__device__ int    g_bsum[196];
__device__ int    g_row_off[Nn + 1];  // CSR row offsets
__device__ int    g_cursor[Nn];       // fill cursors
__device__ __half g_h1h[Nn * DH];     // x @ W1            (fp16 payload)
__device__ __half g_h2h[Nn * DH];     // relu(bn1)@W2      (fp16 payload)
__device__ float  g_agg1[Nn * DH];
__device__ float  g_agg2[Nn * DH];
__device__ float  g_sum1[DH], g_sq1[DH], g_sum2[DH], g_sq2[DH];
__device__ float  g_a;

// ---------------- init: deg=(1,0) self-loop, BN stats, sigmoid(alpha) --------
__global__ void init_kernel(const float* __restrict__ alpha) {
    int i = blockIdx.x * blockDim.x + threadIdx.x;
    if (i < Nn) g_degcnt[i] = make_float2(1.0f, 0.0f);
    if (i < DH) { g_sum1[i] = 0.f; g_sq1[i] = 0.f; g_sum2[i] = 0.f; g_sq2[i] = 0.f; }
    if (i == 0) g_a = 1.0f / (1.0f + expf(-alpha[0]));
}

// ---------------- fused: blocks [0,592) gemm1 | blocks [592,...) mix_deg -----
// The two halves touch disjoint data; co-residency overlaps FMA-bound GEMM with
// the atomic/latency-bound edge preprocessing.
__global__ void mixgemm_kernel(const float* __restrict__ x,
                               const float* __restrict__ W1,
                               const void*  __restrict__ ei,
                               const float* __restrict__ wsc,
                               const float* __restrict__ wfc) {
    __shared__ float sW[DIN * DH];      // 32 KB (gemm path only)
    __shared__ float sx[32][DIN];       // 16 KB
    int tid = threadIdx.x;

    if (blockIdx.x >= GEMM_BLKS) {
        // ---- mix_deg path: per-block dtype detection (256 samples, L2-hot) ----
        int any = __syncthreads_or((int)((const unsigned*)ei)[2 * tid + 1]);
        int is64 = (any == 0);
        int e = (blockIdx.x - GEMM_BLKS) * blockDim.x + tid;
        if (e >= Ee) return;
        int s, d;
        if (is64) {
            const long long* p = (const long long*)ei;   // full-8B loads
            s = (int)p[e];
            d = (int)p[(size_t)Ee + e];
        } else {
            const int* p = (const int*)ei;
            s = p[e];
            d = p[Ee + e];
        }
        float a = g_a;
        float w = a * wsc[e] + (1.0f - a) * wfc[e];
        g_w[e] = w;
        g_idx[e] = make_int2(s, d);
        float* dp = (float*)&g_degcnt[d];
        asm volatile("red.global.add.v2.f32 [%0], {%1,%2};"
                     :: "l"(dp), "f"(w), "f"(1.0f) : "memory");
        return;
    }

    // ---- gemm1 path: h1 = x @ W1 (fp16 store) ----
    for (int i = tid; i < DIN * DH; i += 256) sW[i] = W1[i];
    __syncthreads();
    int warp = tid >> 5, lane = tid & 31;

    for (int base = blockIdx.x * 32; base < Nn; base += GEMM_BLKS * 32) {
        int r0 = base + warp * 4;
        #pragma unroll
        for (int r = 0; r < 4; r++) {
            int row = r0 + r;
            if (row < Nn) {
                #pragma unroll
                for (int j = 0; j < 4; j++)
                    sx[warp * 4 + r][lane + j * 32] = x[(size_t)row * DIN + lane + j * 32];
            }
        }
        __syncwarp();

        float acc[4][2] = {};
        #pragma unroll 8
        for (int k4 = 0; k4 < DIN / 4; k4++) {
            float4 xv[4];
            #pragma unroll
            for (int r = 0; r < 4; r++)
                xv[r] = *reinterpret_cast<const float4*>(&sx[warp * 4 + r][k4 * 4]);
            #pragma unroll
            for (int kk = 0; kk < 4; kk++) {
                int k = k4 * 4 + kk;
                float w0 = sW[k * DH + lane];
                float w1v = sW[k * DH + lane + 32];
                #pragma unroll
                for (int r = 0; r < 4; r++) {
                    float xs = (kk == 0) ? xv[r].x : (kk == 1) ? xv[r].y : (kk == 2) ? xv[r].z : xv[r].w;
                    acc[r][0] = fmaf(xs, w0, acc[r][0]);
                    acc[r][1] = fmaf(xs, w1v, acc[r][1]);
                }
            }
        }

        #pragma unroll
        for (int r = 0; r < 4; r++) {
            int row = r0 + r;
            if (row < Nn) {
                g_h1h[row * DH + lane] = __float2half_rn(acc[r][0]);
                g_h1h[row * DH + lane + 32] = __float2half_rn(acc[r][1]);
            }
        }
        __syncwarp();
    }
}

// ---------------- scan part A (+ dinv fused) ---------------------------------
__global__ void scan_a_kernel() {
    __shared__ int s[256];
    int i = blockIdx.x * 256 + threadIdx.x;
    int v = 0;
    if (i < Nn) {
        float2 dc = g_degcnt[i];
        v = (int)dc.y;
        g_dinv[i] = (dc.x > 0.f) ? rsqrtf(fmaxf(dc.x, 1e-12f)) : 0.f;
    }
    s[threadIdx.x] = v;
    __syncthreads();
    #pragma unroll
    for (int off = 1; off < 256; off <<= 1) {
        int t = (threadIdx.x >= off) ? s[threadIdx.x - off] : 0;
        __syncthreads();
        s[threadIdx.x] += t;
        __syncthreads();
    }
    g_part[i] = s[threadIdx.x] - v;
    if (threadIdx.x == 255) g_bsum[blockIdx.x] = s[255];
}

// ---------------- scan B+C merged: each block redundantly scans g_bsum -------
__global__ void scan_bc_kernel() {
    __shared__ int s[256];
    __shared__ int s_off;
    int tid = threadIdx.x;
    int v = (tid < 196) ? g_bsum[tid] : 0;
    s[tid] = v;
    __syncthreads();
    #pragma unroll
    for (int off = 1; off < 256; off <<= 1) {
        int t = (tid >= off) ? s[tid - off] : 0;
        __syncthreads();
        s[tid] += t;
        __syncthreads();
    }
    if (tid == blockIdx.x) s_off = s[tid] - v;   // exclusive prefix of this block
    __syncthreads();
    int i = blockIdx.x * 256 + tid;
    if (i < Nn) {
        int o = g_part[i] + s_off;
        g_row_off[i] = o;
        g_cursor[i] = o;
    }
    if (i == 0) g_row_off[Nn] = Ee;
}

// ---------------- CSR fill: norm computed here -------------------------------
__global__ void fill_kernel() {
    int e = blockIdx.x * blockDim.x + threadIdx.x;
    if (e >= Ee) return;
    int2 sd = g_idx[e];
    float nrm = g_w[e] * g_dinv[sd.x] * g_dinv[sd.y];
    int pos = atomicAdd(&g_cursor[sd.y], 1);
    g_csr[pos] = make_int2(sd.x, __float_as_int(nrm));
}

// ---------------- CSR aggregation (fp16 gather, fp32 acc) + BN stats ---------
// One warp per dst row; half-warps (16 lanes x 4 halves = full 64-col row).
// Per edge each lane loads 8B (uint2 = 4 fp16), converts, fp32-FMAs.
#define GATH(E, A) {                                                            \
    uint2 _u = *reinterpret_cast<const uint2*>(h + (size_t)(E).x * DH + l4);    \
    float _w = __int_as_float((E).y);                                           \
    float2 _fa = __half22float2(*reinterpret_cast<__half2*>(&_u.x));            \
    float2 _fb = __half22float2(*reinterpret_cast<__half2*>(&_u.y));            \
    A.x = fmaf(_fa.x, _w, A.x); A.y = fmaf(_fa.y, _w, A.y);                     \
    A.z = fmaf(_fb.x, _w, A.z); A.w = fmaf(_fb.y, _w, A.w); }

template <int L>
__global__ void agg_kernel(const float* __restrict__ bias) {
    const __half* __restrict__ h = (L == 1) ? g_h1h : g_h2h;
    float* agg  = (L == 1) ? g_agg1 : g_agg2;
    float* gsum = (L == 1) ? g_sum1 : g_sum2;
    float* gsq  = (L == 1) ? g_sq1  : g_sq2;

    __shared__ int2 stage[8][32];

    int tid = threadIdx.x;
    int w = tid >> 5, lane = tid & 31, half = lane >> 4;
    int l4 = (lane & 15) * 4;
    int wg = (blockIdx.x << 3) + w;
    int nw = gridDim.x << 3;
    float4 bb = *reinterpret_cast<const float4*>(bias + l4);
    float ls0 = 0, ls1 = 0, ls2 = 0, ls3 = 0;
    float lq0 = 0, lq1 = 0, lq2 = 0, lq3 = 0;

    for (int r = wg; r < Nn; r += nw) {
        int beg = g_row_off[r], end = g_row_off[r + 1];
        float4 a0, a1, a2, a3;
        a1 = a2 = a3 = make_float4(0.f, 0.f, 0.f, 0.f);
        if (half == 0) {
            float di = g_dinv[r];
            float sn = di * di;  // self-loop: dinv*1*dinv
            uint2 u = *reinterpret_cast<const uint2*>(h + (size_t)r * DH + l4);
            float2 fa = __half22float2(*reinterpret_cast<__half2*>(&u.x));
            float2 fb = __half22float2(*reinterpret_cast<__half2*>(&u.y));
            a0 = make_float4(fmaf(fa.x, sn, bb.x), fmaf(fa.y, sn, bb.y),
                             fmaf(fb.x, sn, bb.z), fmaf(fb.y, sn, bb.w));
        } else {
            a0 = make_float4(0.f, 0.f, 0.f, 0.f);
        }

        for (int base = beg; base < end; base += 32) {
            int m = end - base;
            if (m > 32) m = 32;
            // stage (coalesced); pad with weight-0 entries (src 0 valid, FMA no-op)
            stage[w][lane] = (lane < m) ? g_csr[base + lane] : make_int2(0, 0);
            __syncwarp();

            int jj = 0;
            for (; jj + 8 <= m; jj += 8) {
                int2 e0 = stage[w][jj + half];
                int2 e1 = stage[w][jj + 2 + half];
                int2 e2 = stage[w][jj + 4 + half];
                int2 e3 = stage[w][jj + 6 + half];
                GATH(e0, a0); GATH(e1, a1); GATH(e2, a2); GATH(e3, a3);
            }
            if (jj < m) {
                int2 e0 = stage[w][jj + half];
                int2 e1 = stage[w][jj + 2 + half];
                int2 e2 = stage[w][jj + 4 + half];
                int2 e3 = stage[w][jj + 6 + half];
                GATH(e0, a0); GATH(e1, a1); GATH(e2, a2); GATH(e3, a3);
            }
            __syncwarp();
        }

        float4 acc = make_float4(a0.x + a1.x + a2.x + a3.x,
                                 a0.y + a1.y + a2.y + a3.y,
                                 a0.z + a1.z + a2.z + a3.z,
                                 a0.w + a1.w + a2.w + a3.w);
        acc.x += __shfl_xor_sync(0xffffffffu, acc.x, 16);
        acc.y += __shfl_xor_sync(0xffffffffu, acc.y, 16);
        acc.z += __shfl_xor_sync(0xffffffffu, acc.z, 16);
        acc.w += __shfl_xor_sync(0xffffffffu, acc.w, 16);
        if (half == 0) {
            *reinterpret_cast<float4*>(agg + (size_t)r * DH + l4) = acc;
            ls0 += acc.x; lq0 = fmaf(acc.x, acc.x, lq0);
            ls1 += acc.y; lq1 = fmaf(acc.y, acc.y, lq1);
            ls2 += acc.z; lq2 = fmaf(acc.z, acc.z, lq2);
            ls3 += acc.w; lq3 = fmaf(acc.w, acc.w, lq3);
        }
    }

    // block reduction of BN stats, then 128 atomics per block
    __shared__ float ssum[8][64], ssq[8][64];
    if (half == 0) {
        ssum[w][l4 + 0] = ls0; ssum[w][l4 + 1] = ls1;
        ssum[w][l4 + 2] = ls2; ssum[w][l4 + 3] = ls3;
        ssq[w][l4 + 0] = lq0;  ssq[w][l4 + 1] = lq1;
        ssq[w][l4 + 2] = lq2;  ssq[w][l4 + 3] = lq3;
    }
    __syncthreads();
    if (tid < 64) {
        float S = 0.f, Q = 0.f;
        #pragma unroll
        for (int ww = 0; ww < 8; ww++) { S += ssum[ww][tid]; Q += ssq[ww][tid]; }
        atomicAdd(&gsum[tid], S);
        atomicAdd(&gsq[tid], Q);
    }
}

// ---------------- GEMM2: h2 = relu(bn1(agg1)) @ W2 (fp16 store) --------------
__global__ void gemm2_kernel(const float* __restrict__ W2,
                             const float* __restrict__ gamma1,
                             const float* __restrict__ beta1) {
    __shared__ float sW[DH * DH];   // 16 KB
    __shared__ float sx[32][DH];    // 8 KB
    __shared__ float s_scale[DH], s_shift[DH];
    int tid = threadIdx.x;
    if (tid < DH) {
        float mean = g_sum1[tid] * (1.0f / Nn);
        float var = g_sq1[tid] * (1.0f / Nn) - mean * mean;
        float sc = gamma1[tid] * rsqrtf(var + BN_EPS);
        s_scale[tid] = sc;
        s_shift[tid] = fmaf(-mean, sc, beta1[tid]);
    }
    for (int i = tid; i < DH * DH; i += 256) sW[i] = W2[i];
    __syncthreads();
    int warp = tid >> 5, lane = tid & 31;

    for (int base = blockIdx.x * 32; base < Nn; base += gridDim.x * 32) {
        int r0 = base + warp * 4;
        #pragma unroll
        for (int r = 0; r < 4; r++) {
            int row = r0 + r;
            if (row < Nn) {
                #pragma unroll
                for (int j = 0; j < 2; j++) {
                    int c = lane + j * 32;
                    float v = g_agg1[(size_t)row * DH + c];
                    sx[warp * 4 + r][c] = fmaxf(fmaf(v, s_scale[c], s_shift[c]), 0.f);
                }
            }
        }
        __syncwarp();

        float acc[4][2] = {};
        #pragma unroll 4
        for (int k4 = 0; k4 < DH / 4; k4++) {
            float4 xv[4];
            #pragma unroll
            for (int r = 0; r < 4; r++)
                xv[r] = *reinterpret_cast<const float4*>(&sx[warp * 4 + r][k4 * 4]);
            #pragma unroll
            for (int kk = 0; kk < 4; kk++) {
                int k = k4 * 4 + kk;
                float w0 = sW[k * DH + lane];
                float w1v = sW[k * DH + lane + 32];
                #pragma unroll
                for (int r = 0; r < 4; r++) {
                    float xs = (kk == 0) ? xv[r].x : (kk == 1) ? xv[r].y : (kk == 2) ? xv[r].z : xv[r].w;
                    acc[r][0] = fmaf(xs, w0, acc[r][0]);
                    acc[r][1] = fmaf(xs, w1v, acc[r][1]);
                }
            }
        }

        #pragma unroll
        for (int r = 0; r < 4; r++) {
            int row = r0 + r;
            if (row < Nn) {
                g_h2h[row * DH + lane] = __float2half_rn(acc[r][0]);
                g_h2h[row * DH + lane + 32] = __float2half_rn(acc[r][1]);
            }
        }
        __syncwarp();
    }
}

// ---------------- final: out = relu(bn2(agg2)) -------------------------------
__global__ void final_kernel(const float* __restrict__ gamma2,
                             const float* __restrict__ beta2,
                             float* __restrict__ out) {
    __shared__ float s_scale[DH], s_shift[DH];
    int tid = threadIdx.x;
    if (tid < DH) {
        float mean = g_sum2[tid] * (1.0f / Nn);
        float var = g_sq2[tid] * (1.0f / Nn) - mean * mean;
        float sc = gamma2[tid] * rsqrtf(var + BN_EPS);
        s_scale[tid] = sc;
        s_shift[tid] = fmaf(-mean, sc, beta2[tid]);
    }
    __syncthreads();
    int i = blockIdx.x * 256 + tid;
    if (i < Nn * DH) {
        int c = i & 63;
        out[i] = fmaxf(fmaf(g_agg2[i], s_scale[c], s_shift[c]), 0.f);
    }
}

// -----------------------------------------------------------------------------
extern "C" void kernel_launch(void* const* d_in, const int* in_sizes, int n_in,
                              void* d_out, int out_size) {
    const float* x      = (const float*)d_in[0];
    const void*  ei_sc  = d_in[1];
    const float* w_sc   = (const float*)d_in[2];
    // d_in[3] = edge_index_fc (unused by reference)
    const float* w_fc   = (const float*)d_in[4];
    const float* alpha  = (const float*)d_in[5];
    const float* W1     = (const float*)d_in[6];
    const float* b1     = (const float*)d_in[7];
    const float* W2     = (const float*)d_in[8];
    const float* b2     = (const float*)d_in[9];
    const float* gamma1 = (const float*)d_in[10];
    const float* beta1  = (const float*)d_in[11];
    const float* gamma2 = (const float*)d_in[12];
    const float* beta2  = (const float*)d_in[13];
    float* out = (float*)d_out;

    const int TB = 256;
    const int nblkE = (Ee + TB - 1) / TB;       // 6250

    init_kernel<<<196, TB>>>(alpha);
    mixgemm_kernel<<<GEMM_BLKS + nblkE, TB>>>(x, W1, ei_sc, w_sc, w_fc);
    scan_a_kernel<<<196, TB>>>();
    scan_bc_kernel<<<196, TB>>>();
    fill_kernel<<<nblkE, TB>>>();
    agg_kernel<1><<<592, TB>>>(b1);
    gemm2_kernel<<<592, TB>>>(W2, gamma1, beta1);
    agg_kernel<2><<<592, TB>>>(b2);
    final_kernel<<<(Nn * DH + TB - 1) / TB, TB>>>(gamma2, beta2, out);
}